// round 9
// baseline (speedup 1.0000x reference)
#include <cuda_runtime.h>
#include <cstdint>

#define NN 2048
#define BS 512
#define THRESH 0.3f
#define OVERLAP 0.5f
#define NW 32                 // 2048-bit masks, indexed by original n

__global__ __launch_bounds__(BS) void det_kernel(
    const float* __restrict__ loc,    // (8,2048,2)
    const float* __restrict__ cls,    // (8,2048,5)
    const float* __restrict__ dflt,   // (2048,2)
    float* __restrict__ out)          // (8,4,2048,3)
{
    __shared__ float2 s_box[NN];                 // decoded boxes, original order
    __shared__ float  s_score[NN];
    __shared__ unsigned long long s_skey[NN];    // spatial keys (asc sort)
    __shared__ float2 s_spbox[NN];               // boxes, spatial order
    __shared__ unsigned long long s_spkey[NN];   // score keys, spatial order
    __shared__ unsigned short s_spn[NN];         // orig n, spatial order
    __shared__ unsigned long long s_valid[NW];
    __shared__ unsigned long long s_keep[2][NW];
    __shared__ unsigned long long s_sup[NW];
    __shared__ int s_m, s_changed;

    const int b = blockIdx.x >> 2;
    const int c = blockIdx.x & 3;     // class index into scores[1..4]
    const int tid = threadIdx.x;

    if (tid == 0) s_m = 0;
    if (tid < NW) s_valid[tid] = 0ull;
    __syncthreads();

    const float* locb = loc + (size_t)b * NN * 2;
    const float* clsb = cls + (size_t)b * NN * 5;

    // ---- decode + softmax + compact valid items (spatial keys only) ----
    for (int n = tid; n < NN; n += BS) {
        float dc = dflt[2 * n], dw = dflt[2 * n + 1];
        float l0 = locb[2 * n], l1 = locb[2 * n + 1];
        float ctr = dc + l0 * dw;
        float w   = dw * expf(l1);
        float st  = ctr - 0.5f * w;
        float en  = ctr + 0.5f * w;
        s_box[n] = make_float2(st, en);

        float x0 = clsb[5 * n + 0];
        float x1 = clsb[5 * n + 1];
        float x2 = clsb[5 * n + 2];
        float x3 = clsb[5 * n + 3];
        float x4 = clsb[5 * n + 4];
        float mx = fmaxf(fmaxf(fmaxf(x0, x1), fmaxf(x2, x3)), x4);
        float sum = expf(x0 - mx) + expf(x1 - mx) + expf(x2 - mx)
                  + expf(x3 - mx) + expf(x4 - mx);
        float sc = expf(clsb[5 * n + 1 + c] - mx) / sum;
        s_score[n] = sc;

        if (sc > THRESH) {
            int slot = atomicAdd(&s_m, 1);
            // monotone signed-float map of start; low bits = n
            unsigned int fb = __float_as_uint(st);
            fb ^= (fb & 0x80000000u) ? 0xFFFFFFFFu : 0x80000000u;
            s_skey[slot] = ((unsigned long long)fb << 32) | (unsigned int)n;
            atomicOr(&s_valid[n >> 6], 1ull << (n & 63));
        }
    }
    __syncthreads();
    const int M = s_m;

    // ---- pad to pow2, single ascending bitonic sort by start ----
    int P = 1;
    while (P < M) P <<= 1;
    for (int j = M + tid; j < P; j += BS) s_skey[j] = 0xFFFFFFFFFFFFFFFFull;
    __syncthreads();

    if (M > 1) {
        for (int k = 2; k <= P; k <<= 1) {
            for (int j = k >> 1; j > 0; j >>= 1) {
                for (int t = tid; t < (P >> 1); t += BS) {
                    int i = ((t & ~(j - 1)) << 1) | (t & (j - 1));
                    int l = i | j;
                    unsigned long long a  = s_skey[i];
                    unsigned long long bb = s_skey[l];
                    bool up = ((i & k) == 0);
                    if ((a > bb) == up) { s_skey[i] = bb; s_skey[l] = a; }
                }
                __syncthreads();
            }
        }
    }

    // ---- gather spatial-order boxes, orig index, and exact score keys ----
    for (int p = tid; p < M; p += BS) {
        int n = (int)(unsigned int)s_skey[p];
        s_spbox[p] = s_box[n];
        s_spn[p]   = (unsigned short)n;
        // score key: (score_bits, 2047-n) — larger key == earlier in greedy order
        s_spkey[p] = ((unsigned long long)__float_as_uint(s_score[n]) << 32)
                   | (unsigned int)(2047 - n);
    }

    // ---- init keep = valid ----
    if (tid < NW) s_keep[0][tid] = s_valid[tid];
    __syncthreads();

    // ---- Jacobi to the greedy fixpoint; window re-scan each round ----
    // keep_new[i] = valid[i] & no currently-kept higher-key overlapper.
    // Unique fixpoint == greedy NMS (induction in score-key order).
    int cb = 0;
    for (int round = 0; round <= M; round++) {
        if (tid < NW) s_sup[tid] = 0ull;
        if (tid == 0) s_changed = 0;
        __syncthreads();

        for (int p = tid; p < M; p += BS) {
            float2 bp = s_spbox[p];
            float lp = bp.y - bp.x;
            unsigned long long kp = s_spkey[p];
            int np = s_spn[p];
            for (int q = p + 1; q < M; q++) {
                float2 bq = s_spbox[q];
                if (bq.x >= bp.y) break;   // starts ascending: no later overlap
                float inter = fmaxf(fminf(bp.y, bq.y) - fmaxf(bp.x, bq.x), 0.0f);
                float uni = lp + (bq.y - bq.x) - inter;
                float iou = inter / fmaxf(uni, 1e-12f);
                if (iou > OVERLAP) {
                    int nq = s_spn[q];
                    int nw_, nl_;
                    if (kp > s_spkey[q]) { nw_ = np; nl_ = nq; }
                    else                 { nw_ = nq; nl_ = np; }
                    if ((s_keep[cb][nw_ >> 6] >> (nw_ & 63)) & 1ull)
                        atomicOr(&s_sup[nl_ >> 6], 1ull << (nl_ & 63));
                }
            }
        }
        __syncthreads();

        if (tid < NW) {
            unsigned long long nwv = s_valid[tid] & ~s_sup[tid];
            if (nwv != s_keep[cb][tid]) s_changed = 1;
            s_keep[cb ^ 1][tid] = nwv;
        }
        __syncthreads();
        cb ^= 1;
        if (!s_changed) break;
    }

    // ---- output (in_range applied AFTER NMS, matching reference) ----
    float* ob = out + (size_t)blockIdx.x * NN * 3;
    for (int n = tid; n < NN; n += BS) {
        float2 bx = s_box[n];
        bool kp = ((s_keep[cb][n >> 6] >> (n & 63)) & 1ull)
                  && (bx.x > -10.0f) && (bx.y < 10.0f);
        ob[3 * n + 0] = kp ? bx.x : 0.0f;
        ob[3 * n + 1] = kp ? bx.y : 0.0f;
        ob[3 * n + 2] = kp ? s_score[n] : 0.0f;
    }
}

extern "C" void kernel_launch(void* const* d_in, const int* in_sizes, int n_in,
                              void* d_out, int out_size) {
    const float* loc  = (const float*)d_in[0];  // (8,2048,2)
    const float* cls  = (const float*)d_in[1];  // (8,2048,5)
    const float* dflt = (const float*)d_in[2];  // (2048,2)
    float* out = (float*)d_out;                 // (8,4,2048,3)
    det_kernel<<<32, BS>>>(loc, cls, dflt, out);
}

// round 10
// speedup vs baseline: 1.2792x; 1.2792x over previous
#include <cuda_runtime.h>
#include <cstdint>

#define NN 2048
#define BS 256
#define THRESH 0.3f
#define OVERLAP 0.5f
#define MCAP 1024                       // sparse path handles M <= 1024
#define WMAX (MCAP / 64)                // 16 words per rank mask
#define ADJ_BYTES (MCAP * WMAX * 8)     // 128 KB dynamic smem adjacency

__global__ __launch_bounds__(BS) void det_kernel(
    const float* __restrict__ loc,    // (8,2048,2)
    const float* __restrict__ cls,    // (8,2048,5)
    const float* __restrict__ dflt,   // (2048,2)
    float* __restrict__ out)          // (8,4,2048,3)
{
    extern __shared__ unsigned long long s_adj[];  // [rank][W] out-edge rows
    __shared__ float2 s_box[NN];                   // decoded boxes, original order
    __shared__ float  s_score[NN];
    __shared__ unsigned long long s_key[NN];       // score keys (desc sort)
    __shared__ unsigned long long s_skey[NN];      // spatial keys (asc sort)
    __shared__ float2 s_spbox[MCAP];               // boxes, spatial order
    __shared__ unsigned short s_sprank[MCAP];      // score-rank, spatial order
    __shared__ unsigned short s_rank[NN];          // orig idx -> score rank
    __shared__ unsigned long long s_cont[WMAX];    // contested ranks
    __shared__ unsigned long long s_supw[WMAX];    // suppressed ranks (result)
    __shared__ unsigned char s_keep_orig[NN];
    __shared__ int s_m;

    const int b = blockIdx.x >> 2;
    const int c = blockIdx.x & 3;     // class index into scores[1..4]
    const int tid = threadIdx.x;

    if (tid == 0) s_m = 0;
    if (tid < WMAX) { s_cont[tid] = 0ull; s_supw[tid] = 0ull; }
    __syncthreads();

    const float* locb = loc + (size_t)b * NN * 2;
    const float* clsb = cls + (size_t)b * NN * 5;

    // ---- decode + softmax + compact valid keys (score + spatial) ----
    for (int n = tid; n < NN; n += BS) {
        float dc = dflt[2 * n], dw = dflt[2 * n + 1];
        float l0 = locb[2 * n], l1 = locb[2 * n + 1];
        float ctr = dc + l0 * dw;
        float w   = dw * expf(l1);
        float st  = ctr - 0.5f * w;
        float en  = ctr + 0.5f * w;
        s_box[n] = make_float2(st, en);

        float x0 = clsb[5 * n + 0];
        float x1 = clsb[5 * n + 1];
        float x2 = clsb[5 * n + 2];
        float x3 = clsb[5 * n + 3];
        float x4 = clsb[5 * n + 4];
        float mx = fmaxf(fmaxf(fmaxf(x0, x1), fmaxf(x2, x3)), x4);
        float sum = expf(x0 - mx) + expf(x1 - mx) + expf(x2 - mx)
                  + expf(x3 - mx) + expf(x4 - mx);
        float sc = expf(clsb[5 * n + 1 + c] - mx) / sum;
        s_score[n] = sc;
        s_keep_orig[n] = 0;

        if (sc > THRESH) {
            int slot = atomicAdd(&s_m, 1);
            // score key: (score_bits, 2047-n) desc == stable argsort(-score)
            s_key[slot] = ((unsigned long long)__float_as_uint(sc) << 32)
                        | (unsigned int)(2047 - n);
            // spatial key: monotone signed-float map of start, low bits = n
            unsigned int fb = __float_as_uint(st);
            fb ^= (fb & 0x80000000u) ? 0xFFFFFFFFu : 0x80000000u;
            s_skey[slot] = ((unsigned long long)fb << 32) | (unsigned int)n;
        }
    }
    __syncthreads();
    const int M = s_m;

    // ---- pad to pow2; fused dual bitonic sort (score desc + spatial asc) ----
    int P = 1;
    while (P < M) P <<= 1;
    for (int j = M + tid; j < P; j += BS) {
        s_key[j]  = 0ull;                    // sorts last (descending)
        s_skey[j] = 0xFFFFFFFFFFFFFFFFull;   // sorts last (ascending)
    }
    __syncthreads();

    if (M > 1) {
        const int H = P >> 1;
        for (int k = 2; k <= P; k <<= 1) {
            for (int j = k >> 1; j > 0; j >>= 1) {
                for (int t = tid; t < P; t += BS) {
                    int tt = (t < H) ? t : (t - H);
                    int i = ((tt & ~(j - 1)) << 1) | (tt & (j - 1));
                    int l = i | j;
                    bool up = ((i & k) == 0);
                    if (t < H) {           // score array, descending
                        unsigned long long a = s_key[i], bb = s_key[l];
                        if ((a < bb) == up) { s_key[i] = bb; s_key[l] = a; }
                    } else {               // spatial array, ascending
                        unsigned long long a = s_skey[i], bb = s_skey[l];
                        if ((a > bb) == up) { s_skey[i] = bb; s_skey[l] = a; }
                    }
                }
                __syncthreads();
            }
        }
    }

    // ---- rank map (orig idx -> score rank) ----
    for (int r = tid; r < M; r += BS)
        s_rank[2047 - (int)(unsigned int)s_key[r]] = (unsigned short)r;
    __syncthreads();

    const bool sparse_ok = (M <= MCAP);
    const int W = (M + 63) >> 6;

    if (M > 0 && sparse_ok) {
        // ---- gather spatial-order boxes + ranks; zero adjacency rows ----
        for (int p = tid; p < M; p += BS) {
            int n = (int)(unsigned int)s_skey[p];
            s_spbox[p]  = s_box[n];
            s_sprank[p] = s_rank[n];
        }
        for (int x = tid; x < M * W; x += BS) s_adj[x] = 0ull;
        __syncthreads();

        // ---- sparse pair scan -> adjacency rows + contested marks ----
        for (int p = tid; p < M; p += BS) {
            float2 bp = s_spbox[p];
            float lp = bp.y - bp.x;
            int rp = s_sprank[p];
            for (int q = p + 1; q < M; q++) {
                float2 bq = s_spbox[q];
                if (bq.x >= bp.y) break;   // starts ascending -> no later overlap
                float inter = fmaxf(fminf(bp.y, bq.y) - fmaxf(bp.x, bq.x), 0.0f);
                float uni = lp + (bq.y - bq.x) - inter;
                float iou = inter / fmaxf(uni, 1e-12f);
                if (iou > OVERLAP) {
                    int rq = s_sprank[q];
                    int a  = (rp < rq) ? rp : rq;   // better (lower) rank
                    int b2 = (rp < rq) ? rq : rp;   // worse rank
                    atomicOr(&s_adj[(size_t)a * W + (b2 >> 6)], 1ull << (b2 & 63));
                    atomicOr(&s_cont[a  >> 6], 1ull << (a  & 63));
                    atomicOr(&s_cont[b2 >> 6], 1ull << (b2 & 63));
                }
            }
        }
        __syncthreads();

        // ---- exact serial greedy sweep over CONTESTED ranks only ----
        // Non-contested ranks have no edges: always kept, never suppress.
        // Ascending rank order == exact greedy; single pass, depth-independent.
        if (tid == 0) {
            for (int rw = 0; rw < W; rw++) {
                unsigned long long cursup = s_supw[rw];
                unsigned long long todo = s_cont[rw] & ~cursup;
                while (todo) {
                    int bit = __ffsll((long long)todo) - 1;
                    int r = (rw << 6) + bit;
                    const unsigned long long* row = s_adj + (size_t)r * W;
                    cursup |= row[rw];                    // on dependence chain
                    for (int w = rw + 1; w < W; w++)      // off-chain updates
                        s_supw[w] |= row[w];
                    todo &= todo - 1;
                    todo &= ~cursup;
                }
                s_supw[rw] = cursup;
            }
        }
        __syncthreads();

        // ---- scatter keep (= valid & !suppressed) to original order ----
        for (int r = tid; r < M; r += BS) {
            if (!((s_supw[r >> 6] >> (r & 63)) & 1ull)) {
                int n = 2047 - (int)(unsigned int)s_key[r];
                s_keep_orig[n] = 1;
            }
        }
        __syncthreads();
    } else if (M > 0) {
        // ---- fallback (M > MCAP): proven greedy serial NMS in score order ----
        unsigned char* fb = (unsigned char*)s_skey;   // reuse as keep flags
        for (int j = tid; j < M; j += BS) fb[j] = 1;
        __syncthreads();
        for (int i = 0; i < M; i++) {
            if (fb[i]) {
                float2 bi = s_box[2047 - (int)(unsigned int)s_key[i]];
                float li = bi.y - bi.x;
                for (int j = i + 1 + tid; j < M; j += BS) {
                    if (!fb[j]) continue;
                    float2 bj = s_box[2047 - (int)(unsigned int)s_key[j]];
                    float inter = fmaxf(fminf(bi.y, bj.y) - fmaxf(bi.x, bj.x), 0.0f);
                    float uni = li + (bj.y - bj.x) - inter;
                    if (inter / fmaxf(uni, 1e-12f) > OVERLAP) fb[j] = 0;
                }
            }
            __syncthreads();
        }
        for (int j = tid; j < M; j += BS) {
            if (fb[j]) s_keep_orig[2047 - (int)(unsigned int)s_key[j]] = 1;
        }
        __syncthreads();
    }

    // ---- output (in_range applied AFTER NMS, matching reference) ----
    float* ob = out + (size_t)blockIdx.x * NN * 3;
    for (int n = tid; n < NN; n += BS) {
        float2 bx = s_box[n];
        bool kp = s_keep_orig[n] && (bx.x > -10.0f) && (bx.y < 10.0f);
        ob[3 * n + 0] = kp ? bx.x : 0.0f;
        ob[3 * n + 1] = kp ? bx.y : 0.0f;
        ob[3 * n + 2] = kp ? s_score[n] : 0.0f;
    }
}

extern "C" void kernel_launch(void* const* d_in, const int* in_sizes, int n_in,
                              void* d_out, int out_size) {
    const float* loc  = (const float*)d_in[0];  // (8,2048,2)
    const float* cls  = (const float*)d_in[1];  // (8,2048,5)
    const float* dflt = (const float*)d_in[2];  // (2048,2)
    float* out = (float*)d_out;                 // (8,4,2048,3)
    cudaFuncSetAttribute(det_kernel, cudaFuncAttributeMaxDynamicSharedMemorySize,
                         ADJ_BYTES);
    det_kernel<<<32, BS, ADJ_BYTES>>>(loc, cls, dflt, out);
}

// round 11
// speedup vs baseline: 2.9844x; 2.3330x over previous
#include <cuda_runtime.h>
#include <cstdint>

#define NN 2048
#define BS 256
#define NB 8
#define THRESH 0.3f
#define OVERLAP 0.5f
#define NBUCK 512
#define NW 32                 // 2048-bit masks indexed by original n
#define REDGE 16              // register edges per thread
#define POOL 4096             // smem overflow edge pool
#define DYN_BYTES 73728       // dynamic smem for nms kernel

__device__ int g_cnt[NB * 4];
__device__ unsigned long long g_key[NB * 4][NN];   // (score_bits<<32)|(2047-n)
__device__ float2 g_box[NB][NN];

__global__ void zero_kernel() {
    if (threadIdx.x < NB * 4) g_cnt[threadIdx.x] = 0;
}

// ---- prep: decode + softmax once per (b,n); compact valid keys per (b,c) ----
__global__ __launch_bounds__(BS) void prep_kernel(
    const float* __restrict__ loc, const float* __restrict__ cls,
    const float* __restrict__ dflt)
{
    const int b = blockIdx.x >> 3;
    const int n = ((blockIdx.x & 7) << 8) | threadIdx.x;
    const float* locb = loc + (size_t)b * NN * 2;
    const float* clsb = cls + (size_t)b * NN * 5;

    float dc = dflt[2 * n], dw = dflt[2 * n + 1];
    float l0 = locb[2 * n], l1 = locb[2 * n + 1];
    float ctr = dc + l0 * dw;
    float w   = dw * expf(l1);
    g_box[b][n] = make_float2(ctr - 0.5f * w, ctr + 0.5f * w);

    float x0 = clsb[5 * n + 0];
    float x1 = clsb[5 * n + 1];
    float x2 = clsb[5 * n + 2];
    float x3 = clsb[5 * n + 3];
    float x4 = clsb[5 * n + 4];
    float mx = fmaxf(fmaxf(fmaxf(x0, x1), fmaxf(x2, x3)), x4);
    float e1 = expf(x1 - mx), e2 = expf(x2 - mx),
          e3 = expf(x3 - mx), e4 = expf(x4 - mx);
    float sum = expf(x0 - mx) + e1 + e2 + e3 + e4;
    float sc[4] = { e1 / sum, e2 / sum, e3 / sum, e4 / sum };

    #pragma unroll
    for (int c = 0; c < 4; c++) {
        if (sc[c] > THRESH) {
            int slot = atomicAdd(&g_cnt[b * 4 + c], 1);
            g_key[b * 4 + c][slot] =
                ((unsigned long long)__float_as_uint(sc[c]) << 32)
                | (unsigned int)(2047 - n);
        }
    }
}

__device__ __forceinline__ unsigned fmap(float f) {
    unsigned u = __float_as_uint(f);
    return u ^ ((u & 0x80000000u) ? 0xFFFFFFFFu : 0x80000000u);
}
__device__ __forceinline__ float funmap(unsigned u) {
    unsigned v = u ^ ((u & 0x80000000u) ? 0x80000000u : 0xFFFFFFFFu);
    return __uint_as_float(v);
}

// ---- nms: one CTA per (b,c) ----
__global__ __launch_bounds__(BS) void nms_kernel(float* __restrict__ out)
{
    extern __shared__ char dyn[];
    unsigned long long* s_tkey = (unsigned long long*)(dyn);           // 16KB
    unsigned long long* s_key  = (unsigned long long*)(dyn + 16384);   // 16KB spatial
    float2*             s_sbox = (float2*)(dyn + 32768);               // 16KB
    float*              s_sc   = (float*)(dyn + 49152);                // 8KB
    unsigned int*       s_pool = (unsigned int*)(dyn + 57344);         // 16KB

    __shared__ unsigned int s_hist[NBUCK];
    __shared__ unsigned int s_bstart[NBUCK + 1];
    __shared__ unsigned int s_boff[NBUCK];
    __shared__ unsigned int s_wsum[8];
    __shared__ unsigned long long s_valid[NW];
    __shared__ unsigned long long s_keep[2][NW];
    __shared__ unsigned long long s_sup[NW];
    __shared__ unsigned int s_minu, s_maxu;
    __shared__ int s_npool, s_over, s_changed;

    const int bc = blockIdx.x;
    const int b  = bc >> 2;
    const int tid = threadIdx.x;
    const int lane = tid & 31, wid = tid >> 5;
    const int M = g_cnt[bc];

    if (tid == 0) { s_npool = 0; s_over = 0; s_minu = 0xFFFFFFFFu; s_maxu = 0u; }
    if (tid < NW) s_valid[tid] = 0ull;
    for (int h = tid; h < NBUCK; h += BS) s_hist[h] = 0u;
    __syncthreads();

    // ---- load keys, min/max start, valid mask ----
    for (int s = tid; s < M; s += BS) {
        unsigned long long k = g_key[bc][s];
        s_tkey[s] = k;
        int n = 2047 - (int)(unsigned int)k;
        atomicOr(&s_valid[n >> 6], 1ull << (n & 63));
        unsigned fm = fmap(g_box[b][n].x);
        atomicMin(&s_minu, fm);
        atomicMax(&s_maxu, fm);
    }
    __syncthreads();

    const float mn = funmap(s_minu);
    const float mxs = funmap(s_maxu);
    const float rng = mxs - mn;
    const float scale = (rng > 0.0f) ? ((float)NBUCK / rng) : 0.0f;

    // ---- histogram by start bucket ----
    for (int s = tid; s < M; s += BS) {
        int n = 2047 - (int)(unsigned int)s_tkey[s];
        float st = g_box[b][n].x;
        int bu = (int)fminf((st - mn) * scale, (float)(NBUCK - 1));
        if (bu < 0) bu = 0;
        atomicAdd(&s_hist[bu], 1u);
    }
    __syncthreads();

    // ---- exclusive scan over 512 bins (2 per thread) ----
    {
        unsigned v0 = s_hist[2 * tid], v1 = s_hist[2 * tid + 1];
        unsigned x = v0 + v1;
        #pragma unroll
        for (int o = 1; o < 32; o <<= 1) {
            unsigned y = __shfl_up_sync(0xFFFFFFFFu, x, o);
            if (lane >= o) x += y;
        }
        if (lane == 31) s_wsum[wid] = x;
        __syncthreads();
        if (tid == 0) {
            unsigned acc = 0;
            for (int w2 = 0; w2 < 8; w2++) { unsigned t = s_wsum[w2]; s_wsum[w2] = acc; acc += t; }
            s_bstart[NBUCK] = acc;
        }
        __syncthreads();
        unsigned excl = x + s_wsum[wid] - (v0 + v1);
        s_bstart[2 * tid] = excl;          s_boff[2 * tid] = excl;
        s_bstart[2 * tid + 1] = excl + v0; s_boff[2 * tid + 1] = excl + v0;
    }
    __syncthreads();

    // ---- scatter into spatial (bucket) order ----
    for (int s = tid; s < M; s += BS) {
        unsigned long long k = s_tkey[s];
        int n = 2047 - (int)(unsigned int)k;
        float2 bx = g_box[b][n];
        int bu = (int)fminf((bx.x - mn) * scale, (float)(NBUCK - 1));
        if (bu < 0) bu = 0;
        int pos = atomicAdd(&s_boff[bu], 1u);
        s_key[pos] = k;
        s_sbox[pos] = bx;
    }
    __syncthreads();

    // ---- sparse pair scan -> register edges (+ smem overflow pool) ----
    unsigned eg[REDGE];
    int ne = 0;
    for (int p = tid; p < M; p += BS) {
        float2 bp = s_sbox[p];
        unsigned long long kp = s_key[p];
        int np = 2047 - (int)(unsigned int)kp;
        float lp = bp.y - bp.x;
        int be = (int)fminf((bp.y - mn) * scale, (float)(NBUCK - 1));
        if (be < 0) be = 0;
        int lim = (int)s_bstart[be + 1];
        for (int q = p + 1; q < lim; q++) {
            float2 bq = s_sbox[q];
            float inter = fmaxf(fminf(bp.y, bq.y) - fmaxf(bp.x, bq.x), 0.0f);
            float uni = lp + (bq.y - bq.x) - inter;
            float iou = inter / fmaxf(uni, 1e-12f);
            if (iou > OVERLAP) {
                unsigned long long kq = s_key[q];
                int nq = 2047 - (int)(unsigned int)kq;
                unsigned e = (kp > kq) ? (((unsigned)nq << 16) | (unsigned)np)
                                       : (((unsigned)np << 16) | (unsigned)nq);
                if (ne < REDGE) eg[ne++] = e;
                else {
                    int sl = atomicAdd(&s_npool, 1);
                    if (sl < POOL) s_pool[sl] = e;
                    else s_over = 1;
                }
            }
        }
    }
    __syncthreads();
    const int npool = (s_npool < POOL) ? s_npool : POOL;
    const int overflow = s_over;

    // ---- init keep = valid ----
    if (tid < NW) s_keep[0][tid] = s_valid[tid];
    __syncthreads();

    // ---- Jacobi to the greedy fixpoint ----
    int cb = 0;
    for (int round = 0; round <= M; round++) {
        if (tid < NW) s_sup[tid] = 0ull;
        if (tid == 0) s_changed = 0;
        __syncthreads();

        if (!overflow) {
            for (int e = 0; e < ne; e++) {
                unsigned ed = eg[e];
                int a = ed & 0xffff;
                if ((s_keep[cb][a >> 6] >> (a & 63)) & 1ull) {
                    int wn = ed >> 16;
                    atomicOr(&s_sup[wn >> 6], 1ull << (wn & 63));
                }
            }
            for (int e = tid; e < npool; e += BS) {
                unsigned ed = s_pool[e];
                int a = ed & 0xffff;
                if ((s_keep[cb][a >> 6] >> (a & 63)) & 1ull) {
                    int wn = ed >> 16;
                    atomicOr(&s_sup[wn >> 6], 1ull << (wn & 63));
                }
            }
        } else {
            // exact fallback: re-scan windows each round (never expected)
            for (int p = tid; p < M; p += BS) {
                float2 bp = s_sbox[p];
                unsigned long long kp = s_key[p];
                int np = 2047 - (int)(unsigned int)kp;
                float lp = bp.y - bp.x;
                int be = (int)fminf((bp.y - mn) * scale, (float)(NBUCK - 1));
                if (be < 0) be = 0;
                int lim = (int)s_bstart[be + 1];
                for (int q = p + 1; q < lim; q++) {
                    float2 bq = s_sbox[q];
                    float inter = fmaxf(fminf(bp.y, bq.y) - fmaxf(bp.x, bq.x), 0.0f);
                    float uni = lp + (bq.y - bq.x) - inter;
                    float iou = inter / fmaxf(uni, 1e-12f);
                    if (iou > OVERLAP) {
                        unsigned long long kq = s_key[q];
                        int nq = 2047 - (int)(unsigned int)kq;
                        int a, wn;
                        if (kp > kq) { a = np; wn = nq; } else { a = nq; wn = np; }
                        if ((s_keep[cb][a >> 6] >> (a & 63)) & 1ull)
                            atomicOr(&s_sup[wn >> 6], 1ull << (wn & 63));
                    }
                }
            }
        }
        __syncthreads();

        if (tid < NW) {
            unsigned long long nv = s_valid[tid] & ~s_sup[tid];
            if (nv != s_keep[cb][tid]) s_changed = 1;
            s_keep[cb ^ 1][tid] = nv;
        }
        __syncthreads();
        int ch = s_changed;
        cb ^= 1;
        __syncthreads();      // protect s_changed before next round's zeroing
        if (!ch) break;
    }

    // ---- scatter kept scores by original n ----
    for (int p = tid; p < M; p += BS) {
        unsigned long long k = s_key[p];
        int n = 2047 - (int)(unsigned int)k;
        if ((s_keep[cb][n >> 6] >> (n & 63)) & 1ull)
            s_sc[n] = __uint_as_float((unsigned int)(k >> 32));
    }
    __syncthreads();

    // ---- output (in_range applied AFTER NMS, matching reference) ----
    float* ob = out + (size_t)bc * NN * 3;
    for (int n = tid; n < NN; n += BS) {
        float2 bx = g_box[b][n];
        bool kp = ((s_keep[cb][n >> 6] >> (n & 63)) & 1ull)
                  && (bx.x > -10.0f) && (bx.y < 10.0f);
        ob[3 * n + 0] = kp ? bx.x : 0.0f;
        ob[3 * n + 1] = kp ? bx.y : 0.0f;
        ob[3 * n + 2] = kp ? s_sc[n] : 0.0f;
    }
}

extern "C" void kernel_launch(void* const* d_in, const int* in_sizes, int n_in,
                              void* d_out, int out_size) {
    const float* loc  = (const float*)d_in[0];  // (8,2048,2)
    const float* cls  = (const float*)d_in[1];  // (8,2048,5)
    const float* dflt = (const float*)d_in[2];  // (2048,2)
    float* out = (float*)d_out;                 // (8,4,2048,3)
    cudaFuncSetAttribute(nms_kernel, cudaFuncAttributeMaxDynamicSharedMemorySize,
                         DYN_BYTES);
    zero_kernel<<<1, 32>>>();
    prep_kernel<<<64, BS>>>(loc, cls, dflt);
    nms_kernel<<<32, BS, DYN_BYTES>>>(out);
}